// round 2
// baseline (speedup 1.0000x reference)
#include <cuda_runtime.h>

// Problem constants (B=8192, L=2048, T=1024)
#define NB 8192
#define NT 1024
#define THREADS 256   // each thread handles 4 t-values (8 floats of pred)

__device__ double g_partials[NB];

__global__ __launch_bounds__(THREADS) void traj_loss_main(
    const float* __restrict__ pred,
    const float* __restrict__ pos_true)
{
    const int b    = blockIdx.x;
    const int tid  = threadIdx.x;
    const int lane = tid & 31;
    const int warp = tid >> 5;

    // --- load 8 contiguous pred floats: t in [4*tid, 4*tid+4), interleaved x,y ---
    const float4* pv = (const float4*)(pred + (size_t)b * (2 * NT));
    float4 a = pv[2 * tid];       // x0 y0 x1 y1
    float4 c = pv[2 * tid + 1];   // x2 y2 x3 y3

    // --- targets: 4 contiguous floats each, coalesced (issue early for MLP) ---
    const float* tp = pos_true + (size_t)b * (2 * NT);
    float4 tx = ((const float4*)tp)[tid];
    float4 ty = ((const float4*)(tp + NT))[tid];

    float lx = a.x + a.z + c.x + c.z;   // thread-local x delta sum
    float ly = a.y + a.w + c.y + c.w;   // thread-local y delta sum

    // --- warp inclusive scan of (lx, ly) ---
    float sx = lx, sy = ly;
    #pragma unroll
    for (int d = 1; d < 32; d <<= 1) {
        float ux = __shfl_up_sync(0xffffffffu, sx, d);
        float uy = __shfl_up_sync(0xffffffffu, sy, d);
        if (lane >= d) { sx += ux; sy += uy; }
    }

    __shared__ float wx[THREADS / 32], wy[THREADS / 32];
    if (lane == 31) { wx[warp] = sx; wy[warp] = sy; }
    __syncthreads();

    // exclusive prefix for this thread = (inclusive - local) + sum of prior warps
    float ox = sx - lx, oy = sy - ly;
    #pragma unroll
    for (int w = 0; w < THREADS / 32 - 1; w++) {
        float addx = wx[w], addy = wy[w];
        if (w < warp) { ox += addx; oy += addy; }
    }

    // --- running cumsum + squared error ---
    float cx = ox, cy = oy, ex, ey;
    float err = 0.0f;
    cx += a.x; cy += a.y; ex = cx - tx.x; ey = cy - ty.x; err += ex * ex + ey * ey;
    cx += a.z; cy += a.w; ex = cx - tx.y; ey = cy - ty.y; err += ex * ex + ey * ey;
    cx += c.x; cy += c.y; ex = cx - tx.z; ey = cy - ty.z; err += ex * ex + ey * ey;
    cx += c.z; cy += c.w; ex = cx - tx.w; ey = cy - ty.w; err += ex * ex + ey * ey;

    // --- block reduce in double (deterministic, high headroom vs 1e-3 gate) ---
    double e = (double)err;
    #pragma unroll
    for (int d = 16; d > 0; d >>= 1)
        e += __shfl_down_sync(0xffffffffu, e, d);

    __shared__ double wsum[THREADS / 32];
    if (lane == 0) wsum[warp] = e;
    __syncthreads();
    if (warp == 0) {
        double v = (lane < THREADS / 32) ? wsum[lane] : 0.0;
        #pragma unroll
        for (int d = 4; d > 0; d >>= 1)
            v += __shfl_down_sync(0xffffffffu, v, d);
        if (lane == 0) g_partials[b] = v;
    }
}

__global__ __launch_bounds__(256) void traj_loss_reduce(float* __restrict__ out)
{
    const int tid  = threadIdx.x;
    const int lane = tid & 31;
    const int warp = tid >> 5;

    double s = 0.0;
    #pragma unroll 4
    for (int i = tid; i < NB; i += 256) s += g_partials[i];

    #pragma unroll
    for (int d = 16; d > 0; d >>= 1)
        s += __shfl_down_sync(0xffffffffu, s, d);

    __shared__ double wsum[8];
    if (lane == 0) wsum[warp] = s;
    __syncthreads();
    if (warp == 0) {
        double v = (lane < 8) ? wsum[lane] : 0.0;
        #pragma unroll
        for (int d = 4; d > 0; d >>= 1)
            v += __shfl_down_sync(0xffffffffu, v, d);
        if (lane == 0) out[0] = (float)v;
    }
}

extern "C" void kernel_launch(void* const* d_in, const int* in_sizes, int n_in,
                              void* d_out, int out_size)
{
    const float* pred     = (const float*)d_in[0];  // traj_pred
    // d_in[1] = traj_du_true — unused by the reference; never read.
    const float* pos_true = (const float*)d_in[2];  // traj_pos_true

    traj_loss_main<<<NB, THREADS>>>(pred, pos_true);
    traj_loss_reduce<<<1, 256>>>((float*)d_out);
}

// round 3
// speedup vs baseline: 1.0667x; 1.0667x over previous
#include <cuda_runtime.h>

// Problem constants (B=8192, L=2048, T=1024)
#define NB 8192
#define NT 1024
#define THREADS 256   // each thread handles 4 t-values (8 floats of pred)

__device__ double g_sum = 0.0;          // zeroed by last block each launch
__device__ unsigned int g_count = 0;    // zeroed by last block each launch

__global__ __launch_bounds__(THREADS) void traj_loss_fused(
    const float* __restrict__ pred,
    const float* __restrict__ pos_true,
    float* __restrict__ out)
{
    const int b    = blockIdx.x;
    const int tid  = threadIdx.x;
    const int lane = tid & 31;
    const int warp = tid >> 5;

    // --- load 8 contiguous pred floats: t in [4*tid, 4*tid+4), interleaved x,y ---
    const float4* pv = (const float4*)(pred + (size_t)b * (2 * NT));
    float4 a = pv[2 * tid];       // x0 y0 x1 y1
    float4 c = pv[2 * tid + 1];   // x2 y2 x3 y3

    // --- targets: 4 contiguous floats each, coalesced (issued early for MLP) ---
    const float* tp = pos_true + (size_t)b * (2 * NT);
    float4 tx = ((const float4*)tp)[tid];
    float4 ty = ((const float4*)(tp + NT))[tid];

    float lx = a.x + a.z + c.x + c.z;   // thread-local x delta sum
    float ly = a.y + a.w + c.y + c.w;   // thread-local y delta sum

    // --- warp inclusive scan of (lx, ly) ---
    float sx = lx, sy = ly;
    #pragma unroll
    for (int d = 1; d < 32; d <<= 1) {
        float ux = __shfl_up_sync(0xffffffffu, sx, d);
        float uy = __shfl_up_sync(0xffffffffu, sy, d);
        if (lane >= d) { sx += ux; sy += uy; }
    }

    __shared__ float wx[THREADS / 32], wy[THREADS / 32];
    if (lane == 31) { wx[warp] = sx; wy[warp] = sy; }
    __syncthreads();

    // exclusive prefix for this thread = (inclusive - local) + sum of prior warps
    float ox = sx - lx, oy = sy - ly;
    #pragma unroll
    for (int w = 0; w < THREADS / 32 - 1; w++) {
        float addx = wx[w], addy = wy[w];
        if (w < warp) { ox += addx; oy += addy; }
    }

    // --- running cumsum + squared error ---
    float cx = ox, cy = oy, ex, ey;
    float err = 0.0f;
    cx += a.x; cy += a.y; ex = cx - tx.x; ey = cy - ty.x; err += ex * ex + ey * ey;
    cx += a.z; cy += a.w; ex = cx - tx.y; ey = cy - ty.y; err += ex * ex + ey * ey;
    cx += c.x; cy += c.y; ex = cx - tx.z; ey = cy - ty.z; err += ex * ex + ey * ey;
    cx += c.z; cy += c.w; ex = cx - tx.w; ey = cy - ty.w; err += ex * ex + ey * ey;

    // --- block reduce in double ---
    double e = (double)err;
    #pragma unroll
    for (int d = 16; d > 0; d >>= 1)
        e += __shfl_down_sync(0xffffffffu, e, d);

    __shared__ double wsum[THREADS / 32];
    if (lane == 0) wsum[warp] = e;
    __syncthreads();

    if (warp == 0) {
        double v = (lane < THREADS / 32) ? wsum[lane] : 0.0;
        #pragma unroll
        for (int d = 4; d > 0; d >>= 1)
            v += __shfl_down_sync(0xffffffffu, v, d);

        if (lane == 0) {
            // accumulate into single global double (double rounding noise ~1e-16 rel)
            atomicAdd(&g_sum, v);
            __threadfence();
            unsigned int old = atomicAdd(&g_count, 1u);
            if (old == NB - 1) {
                // last block: read-and-zero accumulator, reset counter (graph-replay safe)
                unsigned long long bits =
                    atomicExch((unsigned long long*)&g_sum, 0ULL);
                g_count = 0;
                out[0] = (float)__longlong_as_double(bits);
            }
        }
    }
}

extern "C" void kernel_launch(void* const* d_in, const int* in_sizes, int n_in,
                              void* d_out, int out_size)
{
    const float* pred     = (const float*)d_in[0];  // traj_pred
    // d_in[1] = traj_du_true — unused by the reference; never read.
    const float* pos_true = (const float*)d_in[2];  // traj_pos_true

    traj_loss_fused<<<NB, THREADS>>>(pred, pos_true, (float*)d_out);
}